// round 13
// baseline (speedup 1.0000x reference)
#include <cuda_runtime.h>
#include <cuda_fp16.h>
#include <math.h>
#include <stdint.h>

// Problem constants
#define BATCH 2
#define SEQ   1024
#define DM    1024
#define NH    64
#define NHK   8
#define HD    64
#define WIN   128
#define GQA   8
#define QKV_N 5120
#define K_OFF 4096
#define V_OFF 4608
#define KC    32

// Scratch (device globals)
__device__ __align__(16) __half g_qkvh[BATCH * SEQ * QKV_N];
__device__ __align__(16) __half g_xh[BATCH * SEQ * DM];
__device__ __align__(16) __half g_wqh[NH * HD * DM];
__device__ __align__(16) __half g_wkh[NHK * HD * DM];
__device__ __align__(16) __half g_wvh[NHK * HD * DM];
__device__ __align__(16) __half g_woh[DM * NH * HD];
__device__ __align__(16) __half g_attnh[BATCH * SEQ * NH * HD];

// ---------------------------------------------------------------------------
// helpers
// ---------------------------------------------------------------------------
__device__ __forceinline__ unsigned pack_h2(float a, float b) {
    __half2 h = __floats2half2_rn(a, b);
    return *(unsigned*)&h;
}
__device__ __forceinline__ uint32_t smem_u32(const void* p) {
    uint32_t a;
    asm("{ .reg .u64 t; cvta.to.shared.u64 t, %1; cvt.u32.u64 %0, t; }" : "=r"(a) : "l"(p));
    return a;
}
#define CP16(dst, src) \
    asm volatile("cp.async.cg.shared.global [%0], [%1], 16;" \
        :: "r"(dst), "l"(__cvta_generic_to_global(src)))
#define CP_COMMIT() asm volatile("cp.async.commit_group;")
#define CP_WAIT(n)  asm volatile("cp.async.wait_group %0;" :: "n"(n))
#define LDSM_X4(r0, r1, r2, r3, addr) \
    asm volatile("ldmatrix.sync.aligned.m8n8.x4.shared.b16 {%0,%1,%2,%3}, [%4];" \
        : "=r"(r0), "=r"(r1), "=r"(r2), "=r"(r3) : "r"(addr))
#define LDSM_X2T(r0, r1, addr) \
    asm volatile("ldmatrix.sync.aligned.m8n8.x2.trans.shared.b16 {%0,%1}, [%2];" \
        : "=r"(r0), "=r"(r1) : "r"(addr))

__device__ __forceinline__ void mma_f16(float* c, const unsigned* a, const unsigned* b) {
    asm volatile(
        "mma.sync.aligned.m16n8k16.row.col.f32.f16.f16.f32 "
        "{%0,%1,%2,%3}, {%4,%5,%6,%7}, {%8,%9}, {%0,%1,%2,%3};"
        : "+f"(c[0]), "+f"(c[1]), "+f"(c[2]), "+f"(c[3])
        : "r"(a[0]), "r"(a[1]), "r"(a[2]), "r"(a[3]), "r"(b[0]), "r"(b[1]));
}

// ---------------------------------------------------------------------------
// fp32 -> fp16 conversion of x + all weights
// ---------------------------------------------------------------------------
#define CVT_TOTAL4 2883584
__global__ __launch_bounds__(256) void cvt_kernel(
    const float* __restrict__ x,  const float* __restrict__ wq,
    const float* __restrict__ wk, const float* __restrict__ wv,
    const float* __restrict__ wo)
{
    size_t i = (size_t)blockIdx.x * 256 + threadIdx.x;
    const float* src; __half* dst; size_t off;
    if (i < 524288)       { src = x;  dst = g_xh;  off = i; }
    else if (i < 1572864) { src = wq; dst = g_wqh; off = i - 524288; }
    else if (i < 1703936) { src = wk; dst = g_wkh; off = i - 1572864; }
    else if (i < 1835008) { src = wv; dst = g_wvh; off = i - 1703936; }
    else                  { src = wo; dst = g_woh; off = i - 1835008; }
    float4 v = ((const float4*)src)[off];
    ((uint2*)dst)[off] = make_uint2(pack_h2(v.x, v.y), pack_h2(v.z, v.w));
}

// ---------------------------------------------------------------------------
// FP16 GEMM core, 64x128 CTA tile, BK=64, 2-stage cp.async, 2 CTAs/SM.
// 256 threads / 8 warps, warp tile 16(M) x 64(N).
// Smem rows: 64 halves = 128B = 8 chunks of 16B, swizzle c ^ (r&7).
// Static smem 48KB: A[2][8KB] at 0, B[2][16KB] at 16384.
// ---------------------------------------------------------------------------
template <bool HOUT>
__device__ __forceinline__ void gemm_h_core(
    const __half* __restrict__ A, const __half* __restrict__ Bw,
    const float* __restrict__ bias, float* __restrict__ Cf, __half* __restrict__ Ch,
    int K, int ldc, int by, int colbase)
{
    __shared__ uint32_t S[12288];   // 48KB

    const int tid  = threadIdx.x;
    const int wid  = tid >> 5;
    const int lane = tid & 31;
    const int wm   = wid & 3;      // 4 row groups of 16 (64 rows)
    const int wn   = wid >> 2;     // 2 col groups of 64
    const int g    = lane >> 2;
    const int t    = lane & 3;

    const __half* Ag = A + (size_t)(by * 64) * K;
    const uint32_t sb = smem_u32(S);

    // cp.async store geometry
    // A: 64 rows x 8 chunks = 512 chunks -> 2 per thread
    const int ra  = tid >> 2;            // 0..63
    const int ca0 = (tid & 3) * 2;       // chunks ca0, ca0+1
    const uint32_t adA0 = sb + ra * 128 + ((((ca0 + 0) ^ (ra & 7))) << 4);
    const uint32_t adA1 = sb + ra * 128 + ((((ca0 + 1) ^ (ra & 7))) << 4);
    const __half* arow = Ag + (size_t)ra * K + ca0 * 8;
    // B: 128 rows x 8 chunks = 1024 chunks -> 4 per thread
    const int rb  = tid >> 1;            // 0..127
    const int cb0 = (tid & 1) * 4;       // chunks cb0..cb0+3
    uint32_t adB[4];
#pragma unroll
    for (int j = 0; j < 4; j++)
        adB[j] = sb + 16384 + rb * 128 + ((((cb0 + j) ^ (rb & 7))) << 4);
    const __half* brow = Bw + (size_t)rb * K + cb0 * 8;

    // ldmatrix geometry
    const int lane15 = lane & 15;
    const int hiA = lane >> 4;
    const int rowA = wm * 16 + lane15;           // 0..63
    const uint32_t offA = (uint32_t)rowA * 128;
    const int swA = rowA & 7;
    const int hiB = (lane >> 3) & 1;
    const int rowBb = wn * 64 + ((lane >> 4) & 1) * 8 + (lane & 7);

    float acc[8][4];
#pragma unroll
    for (int nt = 0; nt < 8; nt++)
#pragma unroll
        for (int i = 0; i < 4; i++) acc[nt][i] = 0.0f;

    const int niter = K >> 6;

    // prologue: stage 0 -> buffer 0
    {
        CP16(adA0, arow);
        CP16(adA1, arow + 8);
#pragma unroll
        for (int j = 0; j < 4; j++) CP16(adB[j], brow + j * 8);
        CP_COMMIT();
    }

    for (int it = 0; it < niter; it++) {
        // prefetch stage it+1 into the opposite buffer (reads of that buffer
        // finished at the trailing barrier of iteration it-1)
        if (it + 1 < niter) {
            const int s = it + 1;
            const uint32_t bo = (uint32_t)(s & 1) * 8192;
            CP16(adA0 + bo, arow + (size_t)s * 64);
            CP16(adA1 + bo, arow + (size_t)s * 64 + 8);
            const uint32_t bob = (uint32_t)(s & 1) * 16384;
#pragma unroll
            for (int j = 0; j < 4; j++)
                CP16(adB[j] + bob, brow + (size_t)s * 64 + j * 8);
            CP_COMMIT();
            CP_WAIT(1);
        } else {
            CP_WAIT(0);
        }
        __syncthreads();

        const uint32_t sa  = sb + (uint32_t)(it & 1) * 8192;
        const uint32_t sbb = sb + 16384 + (uint32_t)(it & 1) * 16384;

#pragma unroll
        for (int ks = 0; ks < 4; ks++) {
            unsigned a[4], b[8][2];
            const int cA = 2 * ks + hiA;
            LDSM_X4(a[0], a[1], a[2], a[3], sa + offA + (((cA ^ swA)) << 4));
            const int cB = 2 * ks + hiB;
#pragma unroll
            for (int p = 0; p < 4; p++) {
                const int rowB = rowBb + p * 16;
                LDSM_X4(b[2 * p][0], b[2 * p][1], b[2 * p + 1][0], b[2 * p + 1][1],
                        sbb + (uint32_t)rowB * 128 + (((cB ^ (rowB & 7))) << 4));
            }
#pragma unroll
            for (int nt = 0; nt < 8; nt++)
                mma_f16(acc[nt], a, b[nt]);
        }
        __syncthreads();   // all reads done before next prefetch overwrites
    }

    // epilogue with bias
    {
        const int row0 = by * 64 + wm * 16 + g;
#pragma unroll
        for (int nt = 0; nt < 8; nt++) {
            const int col = wn * 64 + nt * 8 + 2 * t;
            const float b0 = bias[col], b1 = bias[col + 1];
            if (HOUT) {
                *(unsigned*)(Ch + (size_t)row0 * ldc + colbase + col) =
                    pack_h2(acc[nt][0] + b0, acc[nt][1] + b1);
                *(unsigned*)(Ch + (size_t)(row0 + 8) * ldc + colbase + col) =
                    pack_h2(acc[nt][2] + b0, acc[nt][3] + b1);
            } else {
                float2 o0 = make_float2(acc[nt][0] + b0, acc[nt][1] + b1);
                float2 o1 = make_float2(acc[nt][2] + b0, acc[nt][3] + b1);
                *(float2*)(Cf + (size_t)row0 * ldc + colbase + col) = o0;
                *(float2*)(Cf + (size_t)(row0 + 8) * ldc + colbase + col) = o1;
            }
        }
    }
}

// Merged QKV projection -> fp16 qkv buffer (grid 40 x 32)
__global__ __launch_bounds__(256, 2) void gemm_qkv(
    const float* __restrict__ bq, const float* __restrict__ bk,
    const float* __restrict__ bv)
{
    const int bx = blockIdx.x;
    const __half* W; const float* bias; int wt, seg;
    if (bx < 32)      { W = g_wqh; bias = bq; wt = bx;      seg = 0; }
    else if (bx < 36) { W = g_wkh; bias = bk; wt = bx - 32; seg = K_OFF; }
    else              { W = g_wvh; bias = bv; wt = bx - 36; seg = V_OFF; }
    gemm_h_core<true>(g_xh, W + (size_t)wt * 128 * DM, bias + wt * 128,
                      nullptr, g_qkvh, DM, QKV_N, blockIdx.y, seg + wt * 128);
}

// Output projection (f32 out, grid 8 x 32)
__global__ __launch_bounds__(256, 2) void gemm_out(
    const float* __restrict__ bias, float* __restrict__ C)
{
    gemm_h_core<false>(g_attnh, g_woh + (size_t)blockIdx.x * 128 * (NH * HD),
                       bias + blockIdx.x * 128, C, nullptr,
                       NH * HD, DM, blockIdx.y, blockIdx.x * 128);
}

// ---------------------------------------------------------------------------
// Fully-fp16 flash attention (unchanged from R10 champion)
// ---------------------------------------------------------------------------
__global__ __launch_bounds__(256) void attn_h_kernel(
    const __half* __restrict__ qkv, const float* __restrict__ sinks,
    __half* __restrict__ out)
{
    __shared__ uint32_t KV[4096];

    const int q0  = blockIdx.x * 32;
    const int hk  = blockIdx.y;
    const int b   = blockIdx.z;
    const int tid = threadIdx.x;
    const int wid = tid >> 5;
    const int lane = tid & 31;
    const int g = lane >> 2;
    const int t = lane & 3;

    const int kbase = (q0 >= 128) ? (q0 - 128) : 0;
    const int nch = (q0 + 32 - kbase) >> 5;
    const uint32_t kvb = smem_u32(KV);

    unsigned qa[2][4][4];
    {
        const __half* qrow = qkv + ((size_t)(b * SEQ + q0)) * QKV_N + hk * 512 + wid * 64;
#pragma unroll
        for (int mt = 0; mt < 2; mt++) {
            const __half* r0 = qrow + (size_t)(mt * 16 + g) * QKV_N;
            const __half* r1 = r0 + (size_t)8 * QKV_N;
#pragma unroll
            for (int ks = 0; ks < 4; ks++) {
                qa[mt][ks][0] = *(const unsigned*)(r0 + ks * 16 + 2 * t);
                qa[mt][ks][1] = *(const unsigned*)(r1 + ks * 16 + 2 * t);
                qa[mt][ks][2] = *(const unsigned*)(r0 + ks * 16 + 8 + 2 * t);
                qa[mt][ks][3] = *(const unsigned*)(r1 + ks * 16 + 8 + 2 * t);
            }
        }
    }

    const float sink = sinks[hk * GQA + wid];
    float m[2][2], l[2][2];
#pragma unroll
    for (int mt = 0; mt < 2; mt++) { m[mt][0] = sink; m[mt][1] = sink; l[mt][0] = 0.f; l[mt][1] = 0.f; }

    float o[2][8][4];
#pragma unroll
    for (int mt = 0; mt < 2; mt++)
#pragma unroll
        for (int nt = 0; nt < 8; nt++)
#pragma unroll
            for (int i = 0; i < 4; i++) o[mt][nt][i] = 0.0f;

    const int lr = tid >> 3;
    const int lc = tid & 7;
    const uint32_t koff = (uint32_t)lr * 128 + (((lc ^ (lr & 7))) << 4);
    const __half* kg = qkv + K_OFF + hk * 64 + lc * 8;
    const __half* vg = qkv + V_OFF + hk * 64 + lc * 8;

    {
        size_t rbase = ((size_t)(b * SEQ + kbase + lr)) * QKV_N;
        CP16(kvb + koff, kg + rbase);
        CP16(kvb + 8192 + koff, vg + rbase);
        CP_COMMIT();
    }

    for (int ch = 0; ch < nch; ch++) {
        const int kb = kbase + ch * KC;
        const uint32_t kbuf = kvb + (ch & 1) * 4096;
        const uint32_t vbuf = kbuf + 8192;

        CP_WAIT(0);
        __syncthreads();

        if (ch + 1 < nch) {
            size_t rbase = ((size_t)(b * SEQ + kb + KC + lr)) * QKV_N;
            uint32_t nb = kvb + ((ch + 1) & 1) * 4096;
            CP16(nb + koff, kg + rbase);
            CP16(nb + 8192 + koff, vg + rbase);
            CP_COMMIT();
        }

        float sc[2][4][4];
#pragma unroll
        for (int mt = 0; mt < 2; mt++)
#pragma unroll
            for (int nt = 0; nt < 4; nt++)
#pragma unroll
                for (int i = 0; i < 4; i++) sc[mt][nt][i] = 0.0f;

#pragma unroll
        for (int ks = 0; ks < 4; ks++) {
            unsigned bf[4][2];
            const int cB = 2 * ks + ((lane >> 3) & 1);
#pragma unroll
            for (int p = 0; p < 2; p++) {
                const int rowB = ((lane >> 4) & 1) * 8 + (lane & 7) + p * 16;
                LDSM_X4(bf[2 * p][0], bf[2 * p][1], bf[2 * p + 1][0], bf[2 * p + 1][1],
                        kbuf + (uint32_t)rowB * 128 + (((cB ^ (rowB & 7))) << 4));
            }
#pragma unroll
            for (int mt = 0; mt < 2; mt++)
#pragma unroll
                for (int nt = 0; nt < 4; nt++)
                    mma_f16(sc[mt][nt], qa[mt][ks], bf[nt]);
        }

#pragma unroll
        for (int mt = 0; mt < 2; mt++) {
            const int qr0 = q0 + mt * 16 + g;
            const int qr1 = qr0 + 8;
            float mx0 = -1e30f, mx1 = -1e30f;
#pragma unroll
            for (int nt = 0; nt < 4; nt++) {
                const int k0c = kb + nt * 8 + 2 * t;
                const int k1c = k0c + 1;
                float s0 = sc[mt][nt][0] * 0.125f;
                float s1 = sc[mt][nt][1] * 0.125f;
                float s2 = sc[mt][nt][2] * 0.125f;
                float s3 = sc[mt][nt][3] * 0.125f;
                s0 = (k0c <= qr0 && qr0 - k0c < WIN) ? s0 : -1e30f;
                s1 = (k1c <= qr0 && qr0 - k1c < WIN) ? s1 : -1e30f;
                s2 = (k0c <= qr1 && qr1 - k0c < WIN) ? s2 : -1e30f;
                s3 = (k1c <= qr1 && qr1 - k1c < WIN) ? s3 : -1e30f;
                sc[mt][nt][0] = s0; sc[mt][nt][1] = s1;
                sc[mt][nt][2] = s2; sc[mt][nt][3] = s3;
                mx0 = fmaxf(mx0, fmaxf(s0, s1));
                mx1 = fmaxf(mx1, fmaxf(s2, s3));
            }
            mx0 = fmaxf(mx0, __shfl_xor_sync(0xFFFFFFFFu, mx0, 1));
            mx0 = fmaxf(mx0, __shfl_xor_sync(0xFFFFFFFFu, mx0, 2));
            mx1 = fmaxf(mx1, __shfl_xor_sync(0xFFFFFFFFu, mx1, 1));
            mx1 = fmaxf(mx1, __shfl_xor_sync(0xFFFFFFFFu, mx1, 2));

            const float mn0 = fmaxf(m[mt][0], mx0);
            const float mn1 = fmaxf(m[mt][1], mx1);
            const float r0 = __expf(m[mt][0] - mn0);
            const float r1 = __expf(m[mt][1] - mn1);
            m[mt][0] = mn0; m[mt][1] = mn1;
            l[mt][0] *= r0; l[mt][1] *= r1;
#pragma unroll
            for (int nt = 0; nt < 8; nt++) {
                o[mt][nt][0] *= r0; o[mt][nt][1] *= r0;
                o[mt][nt][2] *= r1; o[mt][nt][3] *= r1;
            }
#pragma unroll
            for (int nt = 0; nt < 4; nt++) {
                float p0 = __expf(sc[mt][nt][0] - mn0);
                float p1 = __expf(sc[mt][nt][1] - mn0);
                float p2 = __expf(sc[mt][nt][2] - mn1);
                float p3 = __expf(sc[mt][nt][3] - mn1);
                l[mt][0] += p0 + p1;
                l[mt][1] += p2 + p3;
                sc[mt][nt][0] = p0; sc[mt][nt][1] = p1;
                sc[mt][nt][2] = p2; sc[mt][nt][3] = p3;
            }
        }

#pragma unroll
        for (int pk = 0; pk < 2; pk++) {
            unsigned pa[2][4];
#pragma unroll
            for (int mt = 0; mt < 2; mt++) {
                pa[mt][0] = pack_h2(sc[mt][2 * pk][0],     sc[mt][2 * pk][1]);
                pa[mt][1] = pack_h2(sc[mt][2 * pk][2],     sc[mt][2 * pk][3]);
                pa[mt][2] = pack_h2(sc[mt][2 * pk + 1][0], sc[mt][2 * pk + 1][1]);
                pa[mt][3] = pack_h2(sc[mt][2 * pk + 1][2], sc[mt][2 * pk + 1][3]);
            }
            const int rowV = pk * 16 + (lane & 15);
            const uint32_t vrow = vbuf + (uint32_t)rowV * 128;
            const int swV = rowV & 7;
#pragma unroll
            for (int nt = 0; nt < 8; nt++) {
                unsigned bv[2];
                LDSM_X2T(bv[0], bv[1], vrow + (((nt ^ swV)) << 4));
#pragma unroll
                for (int mt = 0; mt < 2; mt++)
                    mma_f16(o[mt][nt], pa[mt], bv);
            }
        }
    }

#pragma unroll
    for (int mt = 0; mt < 2; mt++) {
        float l0 = l[mt][0], l1 = l[mt][1];
        l0 += __shfl_xor_sync(0xFFFFFFFFu, l0, 1);
        l0 += __shfl_xor_sync(0xFFFFFFFFu, l0, 2);
        l1 += __shfl_xor_sync(0xFFFFFFFFu, l1, 1);
        l1 += __shfl_xor_sync(0xFFFFFFFFu, l1, 2);
        const float inv0 = 1.0f / (l0 + __expf(sink - m[mt][0]));
        const float inv1 = 1.0f / (l1 + __expf(sink - m[mt][1]));

        const int qr0 = q0 + mt * 16 + g;
        __half* orow0 = out + ((size_t)(b * SEQ + qr0)) * (NH * HD) + (hk * GQA + wid) * HD;
        __half* orow1 = orow0 + (size_t)8 * (NH * HD);
#pragma unroll
        for (int nt = 0; nt < 8; nt++) {
            *(unsigned*)(orow0 + nt * 8 + 2 * t) = pack_h2(o[mt][nt][0] * inv0, o[mt][nt][1] * inv0);
            *(unsigned*)(orow1 + nt * 8 + 2 * t) = pack_h2(o[mt][nt][2] * inv1, o[mt][nt][3] * inv1);
        }
    }
}

// ---------------------------------------------------------------------------
// kernel_launch
// ---------------------------------------------------------------------------
extern "C" void kernel_launch(void* const* d_in, const int* in_sizes, int n_in,
                              void* d_out, int out_size)
{
    const float* x    = (const float*)d_in[0];
    const float* Wq   = (const float*)d_in[1];
    const float* bq   = (const float*)d_in[2];
    const float* Wk   = (const float*)d_in[3];
    const float* bk   = (const float*)d_in[4];
    const float* Wv   = (const float*)d_in[5];
    const float* bv   = (const float*)d_in[6];
    const float* Wo   = (const float*)d_in[7];
    const float* bo   = (const float*)d_in[8];
    const float* sinks = (const float*)d_in[9];
    float* out = (float*)d_out;

    __half* qkvh = nullptr;
    __half* attnh = nullptr;
    cudaGetSymbolAddress((void**)&qkvh, g_qkvh);
    cudaGetSymbolAddress((void**)&attnh, g_attnh);

    const int M = BATCH * SEQ;   // 2048

    cvt_kernel<<<CVT_TOTAL4 / 256, 256>>>(x, Wq, Wk, Wv, Wo);

    // Merged QKV projection: 64-row tiles -> grid (40, 32), 2 CTAs/SM
    {
        dim3 grid(40, M / 64);
        gemm_qkv<<<grid, 256>>>(bq, bk, bv);
    }
    // Attention (fp16 flash)
    {
        dim3 grid(SEQ / 32, NHK, BATCH);
        attn_h_kernel<<<grid, 256>>>(qkvh, sinks, attnh);
    }
    // Output projection: grid (8, 32), 2 CTAs/SM
    {
        dim3 grid(DM / 128, M / 64);
        gemm_out<<<grid, 256>>>(bo, out);
    }
}

// round 14
// speedup vs baseline: 1.1451x; 1.1451x over previous
#include <cuda_runtime.h>
#include <cuda_fp16.h>
#include <math.h>
#include <stdint.h>

// Problem constants
#define BATCH 2
#define SEQ   1024
#define DM    1024
#define NH    64
#define NHK   8
#define HD    64
#define WIN   128
#define GQA   8
#define QKV_N 5120
#define K_OFF 4096
#define V_OFF 4608
#define KC    32

// Scratch (device globals)
__device__ __align__(16) __half g_qkvh[BATCH * SEQ * QKV_N];
__device__ __align__(16) __half g_xh[BATCH * SEQ * DM];
__device__ __align__(16) __half g_wqh[NH * HD * DM];
__device__ __align__(16) __half g_wkh[NHK * HD * DM];
__device__ __align__(16) __half g_wvh[NHK * HD * DM];
__device__ __align__(16) __half g_woh[DM * NH * HD];
__device__ __align__(16) __half g_attnh[BATCH * SEQ * NH * HD];
__device__ __align__(16) float  g_part[2 * BATCH * SEQ * DM];   // split-K partials

// ---------------------------------------------------------------------------
// helpers
// ---------------------------------------------------------------------------
__device__ __forceinline__ unsigned pack_h2(float a, float b) {
    __half2 h = __floats2half2_rn(a, b);
    return *(unsigned*)&h;
}
__device__ __forceinline__ uint32_t smem_u32(const void* p) {
    uint32_t a;
    asm("{ .reg .u64 t; cvta.to.shared.u64 t, %1; cvt.u32.u64 %0, t; }" : "=r"(a) : "l"(p));
    return a;
}
#define CP16(dst, src) \
    asm volatile("cp.async.cg.shared.global [%0], [%1], 16;" \
        :: "r"(dst), "l"(__cvta_generic_to_global(src)))
#define CP_COMMIT() asm volatile("cp.async.commit_group;")
#define CP_WAIT(n)  asm volatile("cp.async.wait_group %0;" :: "n"(n))
#define LDSM_X4(r0, r1, r2, r3, addr) \
    asm volatile("ldmatrix.sync.aligned.m8n8.x4.shared.b16 {%0,%1,%2,%3}, [%4];" \
        : "=r"(r0), "=r"(r1), "=r"(r2), "=r"(r3) : "r"(addr))
#define LDSM_X2T(r0, r1, addr) \
    asm volatile("ldmatrix.sync.aligned.m8n8.x2.trans.shared.b16 {%0,%1}, [%2];" \
        : "=r"(r0), "=r"(r1) : "r"(addr))

__device__ __forceinline__ void mma_f16(float* c, const unsigned* a, const unsigned* b) {
    asm volatile(
        "mma.sync.aligned.m16n8k16.row.col.f32.f16.f16.f32 "
        "{%0,%1,%2,%3}, {%4,%5,%6,%7}, {%8,%9}, {%0,%1,%2,%3};"
        : "+f"(c[0]), "+f"(c[1]), "+f"(c[2]), "+f"(c[3])
        : "r"(a[0]), "r"(a[1]), "r"(a[2]), "r"(a[3]), "r"(b[0]), "r"(b[1]));
}

// ---------------------------------------------------------------------------
// fp32 -> fp16 conversion of x + all weights
// ---------------------------------------------------------------------------
#define CVT_TOTAL4 2883584
__global__ __launch_bounds__(256) void cvt_kernel(
    const float* __restrict__ x,  const float* __restrict__ wq,
    const float* __restrict__ wk, const float* __restrict__ wv,
    const float* __restrict__ wo)
{
    size_t i = (size_t)blockIdx.x * 256 + threadIdx.x;
    const float* src; __half* dst; size_t off;
    if (i < 524288)       { src = x;  dst = g_xh;  off = i; }
    else if (i < 1572864) { src = wq; dst = g_wqh; off = i - 524288; }
    else if (i < 1703936) { src = wk; dst = g_wkh; off = i - 1572864; }
    else if (i < 1835008) { src = wv; dst = g_wvh; off = i - 1703936; }
    else                  { src = wo; dst = g_woh; off = i - 1835008; }
    float4 v = ((const float4*)src)[off];
    ((uint2*)dst)[off] = make_uint2(pack_h2(v.x, v.y), pack_h2(v.z, v.w));
}

// ---------------------------------------------------------------------------
// FP16 GEMM core (R10 champion inner loop), BK=64, 512 threads / 16 warps,
// warp tile 16(M) x 64(N), 3-stage cp.async, 96KB dynamic smem.
// Smem rows: 64 halves = 128B = 8 chunks of 16B, swizzle c ^ (r&7).
// MODE: 1 = fp16 out + bias, 2 = fp32 partial (no bias).
// lda/ldb = actual row strides of A/B (may exceed K for split-K).
// ---------------------------------------------------------------------------
#define GEMM_SMEM 98304
#define STAGE_B   16384
#define BOFF      49152

template <int MODE>
__device__ __forceinline__ void gemm_h_core(
    const __half* __restrict__ A, const __half* __restrict__ Bw,
    const float* __restrict__ bias, float* __restrict__ Cf, __half* __restrict__ Ch,
    int K, int lda, int ldb, int ldc, int by, int colbase)
{
    extern __shared__ uint32_t Sg[];

    const int tid  = threadIdx.x;
    const int wid  = tid >> 5;
    const int lane = tid & 31;
    const int wm   = wid & 7;
    const int wn   = wid >> 3;
    const int g    = lane >> 2;
    const int t    = lane & 3;

    const __half* Ag = A + (size_t)(by * 128) * lda;
    const uint32_t sb = smem_u32(Sg);

    // cp.async store geometry
    const int r  = tid >> 2;
    const int c0 = (tid & 3) * 2;
    const int rsw = r & 7;
    const uint32_t adA0 = sb + r * 128 + ((((c0 + 0) ^ rsw)) << 4);
    const uint32_t adA1 = sb + r * 128 + ((((c0 + 1) ^ rsw)) << 4);
    const __half* arow = Ag + (size_t)r * lda + c0 * 8;
    const __half* brow = Bw + (size_t)r * ldb + c0 * 8;

    // ldmatrix geometry
    const int lane15 = lane & 15;
    const int hiA  = lane >> 4;
    const int rowA = wm * 16 + lane15;
    const uint32_t offA = (uint32_t)rowA * 128;
    const int swA = rowA & 7;
    const int hiB = (lane >> 3) & 1;
    const int rowBb = wn * 64 + ((lane >> 4) & 1) * 8 + (lane & 7);

    float acc[8][4];
#pragma unroll
    for (int nt = 0; nt < 8; nt++)
#pragma unroll
        for (int i = 0; i < 4; i++) acc[nt][i] = 0.0f;

    const int niter = K >> 6;

#pragma unroll
    for (int s = 0; s < 2; s++) {
        const uint32_t bo = s * STAGE_B;
        CP16(adA0 + bo, arow + s * 64);
        CP16(adA1 + bo, arow + s * 64 + 8);
        CP16(adA0 + bo + BOFF, brow + s * 64);
        CP16(adA1 + bo + BOFF, brow + s * 64 + 8);
        CP_COMMIT();
    }

    for (int it = 0; it < niter; it++) {
        const int buf = it % 3;
        if (it + 1 < niter) { CP_WAIT(1); } else { CP_WAIT(0); }
        __syncthreads();

        if (it + 2 < niter) {
            const int s = it + 2;
            const uint32_t bo = (s % 3) * STAGE_B;
            CP16(adA0 + bo, arow + (size_t)s * 64);
            CP16(adA1 + bo, arow + (size_t)s * 64 + 8);
            CP16(adA0 + bo + BOFF, brow + (size_t)s * 64);
            CP16(adA1 + bo + BOFF, brow + (size_t)s * 64 + 8);
            CP_COMMIT();
        }

        const uint32_t sa  = sb + buf * STAGE_B;
        const uint32_t sbb = sa + BOFF;

#pragma unroll
        for (int ks = 0; ks < 4; ks++) {
            unsigned a[4], b[8][2];
            const int cA = 2 * ks + hiA;
            LDSM_X4(a[0], a[1], a[2], a[3], sa + offA + (((cA ^ swA)) << 4));
            const int cB = 2 * ks + hiB;
#pragma unroll
            for (int p = 0; p < 4; p++) {
                const int rowB = rowBb + p * 16;
                LDSM_X4(b[2 * p][0], b[2 * p][1], b[2 * p + 1][0], b[2 * p + 1][1],
                        sbb + (uint32_t)rowB * 128 + (((cB ^ (rowB & 7))) << 4));
            }
#pragma unroll
            for (int nt = 0; nt < 8; nt++)
                mma_f16(acc[nt], a, b[nt]);
        }
    }

    // epilogue
    {
        const int row0 = by * 128 + wm * 16 + g;
#pragma unroll
        for (int nt = 0; nt < 8; nt++) {
            const int col = wn * 64 + nt * 8 + 2 * t;
            if (MODE == 1) {
                const float b0 = bias[col], b1 = bias[col + 1];
                *(unsigned*)(Ch + (size_t)row0 * ldc + colbase + col) =
                    pack_h2(acc[nt][0] + b0, acc[nt][1] + b1);
                *(unsigned*)(Ch + (size_t)(row0 + 8) * ldc + colbase + col) =
                    pack_h2(acc[nt][2] + b0, acc[nt][3] + b1);
            } else {
                float2 o0 = make_float2(acc[nt][0], acc[nt][1]);
                float2 o1 = make_float2(acc[nt][2], acc[nt][3]);
                *(float2*)(Cf + (size_t)row0 * ldc + colbase + col) = o0;
                *(float2*)(Cf + (size_t)(row0 + 8) * ldc + colbase + col) = o1;
            }
        }
    }
}

// Merged QKV projection -> fp16 qkv buffer (grid 40 x 16)
__global__ __launch_bounds__(512, 1) void gemm_qkv(
    const float* __restrict__ bq, const float* __restrict__ bk,
    const float* __restrict__ bv)
{
    const int bx = blockIdx.x;
    const __half* W; const float* bias; int wt, seg;
    if (bx < 32)      { W = g_wqh; bias = bq; wt = bx;      seg = 0; }
    else if (bx < 36) { W = g_wkh; bias = bk; wt = bx - 32; seg = K_OFF; }
    else              { W = g_wvh; bias = bv; wt = bx - 36; seg = V_OFF; }
    gemm_h_core<1>(g_xh, W + (size_t)wt * 128 * DM, bias + wt * 128,
                   nullptr, g_qkvh, DM, DM, DM, QKV_N, blockIdx.y, seg + wt * 128);
}

// Output projection split-K=2: grid (8, 16, 2) -> fp32 partials
__global__ __launch_bounds__(512, 1) void gemm_out_sk()
{
    const int sk = blockIdx.z;
    const __half* A  = g_attnh + sk * 2048;                       // K offset
    const __half* Bw = g_woh + (size_t)blockIdx.x * 128 * (NH * HD) + sk * 2048;
    float* part = g_part + (size_t)sk * BATCH * SEQ * DM;
    gemm_h_core<2>(A, Bw, nullptr, part, nullptr,
                   2048, NH * HD, NH * HD, DM, blockIdx.y, blockIdx.x * 128);
}

// Deterministic reduce: out = p0 + p1 + bias
__global__ __launch_bounds__(256) void reduce_out(
    const float* __restrict__ bias, float* __restrict__ out)
{
    const int i = blockIdx.x * 256 + threadIdx.x;        // float4 index
    float4 a = ((const float4*)g_part)[i];
    float4 b = ((const float4*)g_part)[i + (BATCH * SEQ * DM) / 4];
    const int col = (i * 4) & (DM - 1);
    float4 bv = *(const float4*)(bias + col);
    float4 o;
    o.x = a.x + b.x + bv.x;
    o.y = a.y + b.y + bv.y;
    o.z = a.z + b.z + bv.z;
    o.w = a.w + b.w + bv.w;
    ((float4*)out)[i] = o;
}

// ---------------------------------------------------------------------------
// Fully-fp16 flash attention (R10 champion, unchanged)
// ---------------------------------------------------------------------------
__global__ __launch_bounds__(256) void attn_h_kernel(
    const __half* __restrict__ qkv, const float* __restrict__ sinks,
    __half* __restrict__ out)
{
    __shared__ uint32_t KV[4096];

    const int q0  = blockIdx.x * 32;
    const int hk  = blockIdx.y;
    const int b   = blockIdx.z;
    const int tid = threadIdx.x;
    const int wid = tid >> 5;
    const int lane = tid & 31;
    const int g = lane >> 2;
    const int t = lane & 3;

    const int kbase = (q0 >= 128) ? (q0 - 128) : 0;
    const int nch = (q0 + 32 - kbase) >> 5;
    const uint32_t kvb = smem_u32(KV);

    unsigned qa[2][4][4];
    {
        const __half* qrow = qkv + ((size_t)(b * SEQ + q0)) * QKV_N + hk * 512 + wid * 64;
#pragma unroll
        for (int mt = 0; mt < 2; mt++) {
            const __half* r0 = qrow + (size_t)(mt * 16 + g) * QKV_N;
            const __half* r1 = r0 + (size_t)8 * QKV_N;
#pragma unroll
            for (int ks = 0; ks < 4; ks++) {
                qa[mt][ks][0] = *(const unsigned*)(r0 + ks * 16 + 2 * t);
                qa[mt][ks][1] = *(const unsigned*)(r1 + ks * 16 + 2 * t);
                qa[mt][ks][2] = *(const unsigned*)(r0 + ks * 16 + 8 + 2 * t);
                qa[mt][ks][3] = *(const unsigned*)(r1 + ks * 16 + 8 + 2 * t);
            }
        }
    }

    const float sink = sinks[hk * GQA + wid];
    float m[2][2], l[2][2];
#pragma unroll
    for (int mt = 0; mt < 2; mt++) { m[mt][0] = sink; m[mt][1] = sink; l[mt][0] = 0.f; l[mt][1] = 0.f; }

    float o[2][8][4];
#pragma unroll
    for (int mt = 0; mt < 2; mt++)
#pragma unroll
        for (int nt = 0; nt < 8; nt++)
#pragma unroll
            for (int i = 0; i < 4; i++) o[mt][nt][i] = 0.0f;

    const int lr = tid >> 3;
    const int lc = tid & 7;
    const uint32_t koff = (uint32_t)lr * 128 + (((lc ^ (lr & 7))) << 4);
    const __half* kg = qkv + K_OFF + hk * 64 + lc * 8;
    const __half* vg = qkv + V_OFF + hk * 64 + lc * 8;

    {
        size_t rbase = ((size_t)(b * SEQ + kbase + lr)) * QKV_N;
        CP16(kvb + koff, kg + rbase);
        CP16(kvb + 8192 + koff, vg + rbase);
        CP_COMMIT();
    }

    for (int ch = 0; ch < nch; ch++) {
        const int kb = kbase + ch * KC;
        const uint32_t kbuf = kvb + (ch & 1) * 4096;
        const uint32_t vbuf = kbuf + 8192;

        CP_WAIT(0);
        __syncthreads();

        if (ch + 1 < nch) {
            size_t rbase = ((size_t)(b * SEQ + kb + KC + lr)) * QKV_N;
            uint32_t nb = kvb + ((ch + 1) & 1) * 4096;
            CP16(nb + koff, kg + rbase);
            CP16(nb + 8192 + koff, vg + rbase);
            CP_COMMIT();
        }

        float sc[2][4][4];
#pragma unroll
        for (int mt = 0; mt < 2; mt++)
#pragma unroll
            for (int nt = 0; nt < 4; nt++)
#pragma unroll
                for (int i = 0; i < 4; i++) sc[mt][nt][i] = 0.0f;

#pragma unroll
        for (int ks = 0; ks < 4; ks++) {
            unsigned bf[4][2];
            const int cB = 2 * ks + ((lane >> 3) & 1);
#pragma unroll
            for (int p = 0; p < 2; p++) {
                const int rowB = ((lane >> 4) & 1) * 8 + (lane & 7) + p * 16;
                LDSM_X4(bf[2 * p][0], bf[2 * p][1], bf[2 * p + 1][0], bf[2 * p + 1][1],
                        kbuf + (uint32_t)rowB * 128 + (((cB ^ (rowB & 7))) << 4));
            }
#pragma unroll
            for (int mt = 0; mt < 2; mt++)
#pragma unroll
                for (int nt = 0; nt < 4; nt++)
                    mma_f16(sc[mt][nt], qa[mt][ks], bf[nt]);
        }

#pragma unroll
        for (int mt = 0; mt < 2; mt++) {
            const int qr0 = q0 + mt * 16 + g;
            const int qr1 = qr0 + 8;
            float mx0 = -1e30f, mx1 = -1e30f;
#pragma unroll
            for (int nt = 0; nt < 4; nt++) {
                const int k0c = kb + nt * 8 + 2 * t;
                const int k1c = k0c + 1;
                float s0 = sc[mt][nt][0] * 0.125f;
                float s1 = sc[mt][nt][1] * 0.125f;
                float s2 = sc[mt][nt][2] * 0.125f;
                float s3 = sc[mt][nt][3] * 0.125f;
                s0 = (k0c <= qr0 && qr0 - k0c < WIN) ? s0 : -1e30f;
                s1 = (k1c <= qr0 && qr0 - k1c < WIN) ? s1 : -1e30f;
                s2 = (k0c <= qr1 && qr1 - k0c < WIN) ? s2 : -1e30f;
                s3 = (k1c <= qr1 && qr1 - k1c < WIN) ? s3 : -1e30f;
                sc[mt][nt][0] = s0; sc[mt][nt][1] = s1;
                sc[mt][nt][2] = s2; sc[mt][nt][3] = s3;
                mx0 = fmaxf(mx0, fmaxf(s0, s1));
                mx1 = fmaxf(mx1, fmaxf(s2, s3));
            }
            mx0 = fmaxf(mx0, __shfl_xor_sync(0xFFFFFFFFu, mx0, 1));
            mx0 = fmaxf(mx0, __shfl_xor_sync(0xFFFFFFFFu, mx0, 2));
            mx1 = fmaxf(mx1, __shfl_xor_sync(0xFFFFFFFFu, mx1, 1));
            mx1 = fmaxf(mx1, __shfl_xor_sync(0xFFFFFFFFu, mx1, 2));

            const float mn0 = fmaxf(m[mt][0], mx0);
            const float mn1 = fmaxf(m[mt][1], mx1);
            const float r0 = __expf(m[mt][0] - mn0);
            const float r1 = __expf(m[mt][1] - mn1);
            m[mt][0] = mn0; m[mt][1] = mn1;
            l[mt][0] *= r0; l[mt][1] *= r1;
#pragma unroll
            for (int nt = 0; nt < 8; nt++) {
                o[mt][nt][0] *= r0; o[mt][nt][1] *= r0;
                o[mt][nt][2] *= r1; o[mt][nt][3] *= r1;
            }
#pragma unroll
            for (int nt = 0; nt < 4; nt++) {
                float p0 = __expf(sc[mt][nt][0] - mn0);
                float p1 = __expf(sc[mt][nt][1] - mn0);
                float p2 = __expf(sc[mt][nt][2] - mn1);
                float p3 = __expf(sc[mt][nt][3] - mn1);
                l[mt][0] += p0 + p1;
                l[mt][1] += p2 + p3;
                sc[mt][nt][0] = p0; sc[mt][nt][1] = p1;
                sc[mt][nt][2] = p2; sc[mt][nt][3] = p3;
            }
        }

#pragma unroll
        for (int pk = 0; pk < 2; pk++) {
            unsigned pa[2][4];
#pragma unroll
            for (int mt = 0; mt < 2; mt++) {
                pa[mt][0] = pack_h2(sc[mt][2 * pk][0],     sc[mt][2 * pk][1]);
                pa[mt][1] = pack_h2(sc[mt][2 * pk][2],     sc[mt][2 * pk][3]);
                pa[mt][2] = pack_h2(sc[mt][2 * pk + 1][0], sc[mt][2 * pk + 1][1]);
                pa[mt][3] = pack_h2(sc[mt][2 * pk + 1][2], sc[mt][2 * pk + 1][3]);
            }
            const int rowV = pk * 16 + (lane & 15);
            const uint32_t vrow = vbuf + (uint32_t)rowV * 128;
            const int swV = rowV & 7;
#pragma unroll
            for (int nt = 0; nt < 8; nt++) {
                unsigned bv[2];
                LDSM_X2T(bv[0], bv[1], vrow + (((nt ^ swV)) << 4));
#pragma unroll
                for (int mt = 0; mt < 2; mt++)
                    mma_f16(o[mt][nt], pa[mt], bv);
            }
        }
    }

#pragma unroll
    for (int mt = 0; mt < 2; mt++) {
        float l0 = l[mt][0], l1 = l[mt][1];
        l0 += __shfl_xor_sync(0xFFFFFFFFu, l0, 1);
        l0 += __shfl_xor_sync(0xFFFFFFFFu, l0, 2);
        l1 += __shfl_xor_sync(0xFFFFFFFFu, l1, 1);
        l1 += __shfl_xor_sync(0xFFFFFFFFu, l1, 2);
        const float inv0 = 1.0f / (l0 + __expf(sink - m[mt][0]));
        const float inv1 = 1.0f / (l1 + __expf(sink - m[mt][1]));

        const int qr0 = q0 + mt * 16 + g;
        __half* orow0 = out + ((size_t)(b * SEQ + qr0)) * (NH * HD) + (hk * GQA + wid) * HD;
        __half* orow1 = orow0 + (size_t)8 * (NH * HD);
#pragma unroll
        for (int nt = 0; nt < 8; nt++) {
            *(unsigned*)(orow0 + nt * 8 + 2 * t) = pack_h2(o[mt][nt][0] * inv0, o[mt][nt][1] * inv0);
            *(unsigned*)(orow1 + nt * 8 + 2 * t) = pack_h2(o[mt][nt][2] * inv1, o[mt][nt][3] * inv1);
        }
    }
}

// ---------------------------------------------------------------------------
// kernel_launch
// ---------------------------------------------------------------------------
extern "C" void kernel_launch(void* const* d_in, const int* in_sizes, int n_in,
                              void* d_out, int out_size)
{
    const float* x    = (const float*)d_in[0];
    const float* Wq   = (const float*)d_in[1];
    const float* bq   = (const float*)d_in[2];
    const float* Wk   = (const float*)d_in[3];
    const float* bk   = (const float*)d_in[4];
    const float* Wv   = (const float*)d_in[5];
    const float* bv   = (const float*)d_in[6];
    const float* Wo   = (const float*)d_in[7];
    const float* bo   = (const float*)d_in[8];
    const float* sinks = (const float*)d_in[9];
    float* out = (float*)d_out;

    __half* qkvh = nullptr;
    __half* attnh = nullptr;
    cudaGetSymbolAddress((void**)&qkvh, g_qkvh);
    cudaGetSymbolAddress((void**)&attnh, g_attnh);

    static bool attr_set = false;
    if (!attr_set) {
        cudaFuncSetAttribute(gemm_qkv, cudaFuncAttributeMaxDynamicSharedMemorySize, GEMM_SMEM);
        cudaFuncSetAttribute(gemm_out_sk, cudaFuncAttributeMaxDynamicSharedMemorySize, GEMM_SMEM);
        attr_set = true;
    }

    const int M = BATCH * SEQ;   // 2048

    // fp32 -> fp16 conversion
    cvt_kernel<<<CVT_TOTAL4 / 256, 256>>>(x, Wq, Wk, Wv, Wo);

    // Merged QKV projection -> fp16
    {
        dim3 grid(40, M / 128);
        gemm_qkv<<<grid, 512, GEMM_SMEM>>>(bq, bk, bv);
    }

    // Attention (fully fp16)
    {
        dim3 grid(SEQ / 32, NHK, BATCH);
        attn_h_kernel<<<grid, 256>>>(qkvh, sinks, attnh);
    }

    // Output projection: split-K=2 partials, then deterministic reduce
    {
        dim3 grid(DM / 128, M / 128, 2);
        gemm_out_sk<<<grid, 512, GEMM_SMEM>>>();
        reduce_out<<<(M * DM / 4) / 256, 256>>>(bo, out);
    }
}

// round 15
// speedup vs baseline: 1.2126x; 1.0589x over previous
#include <cuda_runtime.h>
#include <cuda_fp16.h>
#include <math.h>
#include <stdint.h>

// Problem constants
#define BATCH 2
#define SEQ   1024
#define DM    1024
#define NH    64
#define NHK   8
#define HD    64
#define WIN   128
#define GQA   8
#define QKV_N 5120
#define K_OFF 4096
#define V_OFF 4608
#define KC    32

// Scratch (device globals)
__device__ __align__(16) __half g_qkvh[BATCH * SEQ * QKV_N];
__device__ __align__(16) __half g_xh[BATCH * SEQ * DM];
__device__ __align__(16) __half g_wqh[NH * HD * DM];
__device__ __align__(16) __half g_wkh[NHK * HD * DM];
__device__ __align__(16) __half g_wvh[NHK * HD * DM];
__device__ __align__(16) __half g_woh[DM * NH * HD];
__device__ __align__(16) __half g_attnh[BATCH * SEQ * NH * HD];

// ---------------------------------------------------------------------------
// helpers
// ---------------------------------------------------------------------------
__device__ __forceinline__ unsigned pack_h2(float a, float b) {
    __half2 h = __floats2half2_rn(a, b);
    return *(unsigned*)&h;
}
__device__ __forceinline__ uint32_t smem_u32(const void* p) {
    uint32_t a;
    asm("{ .reg .u64 t; cvta.to.shared.u64 t, %1; cvt.u32.u64 %0, t; }" : "=r"(a) : "l"(p));
    return a;
}
#define CP16(dst, src) \
    asm volatile("cp.async.cg.shared.global [%0], [%1], 16;" \
        :: "r"(dst), "l"(__cvta_generic_to_global(src)))
#define CP_COMMIT() asm volatile("cp.async.commit_group;")
#define CP_WAIT(n)  asm volatile("cp.async.wait_group %0;" :: "n"(n))
#define LDSM_X4(r0, r1, r2, r3, addr) \
    asm volatile("ldmatrix.sync.aligned.m8n8.x4.shared.b16 {%0,%1,%2,%3}, [%4];" \
        : "=r"(r0), "=r"(r1), "=r"(r2), "=r"(r3) : "r"(addr))
#define LDSM_X2T(r0, r1, addr) \
    asm volatile("ldmatrix.sync.aligned.m8n8.x2.trans.shared.b16 {%0,%1}, [%2];" \
        : "=r"(r0), "=r"(r1) : "r"(addr))

__device__ __forceinline__ void mma_f16(float* c, const unsigned* a, const unsigned* b) {
    asm volatile(
        "mma.sync.aligned.m16n8k16.row.col.f32.f16.f16.f32 "
        "{%0,%1,%2,%3}, {%4,%5,%6,%7}, {%8,%9}, {%0,%1,%2,%3};"
        : "+f"(c[0]), "+f"(c[1]), "+f"(c[2]), "+f"(c[3])
        : "r"(a[0]), "r"(a[1]), "r"(a[2]), "r"(a[3]), "r"(b[0]), "r"(b[1]));
}

// ---------------------------------------------------------------------------
// fp32 -> fp16 conversion of x + all weights
// ---------------------------------------------------------------------------
#define CVT_TOTAL4 2883584
__global__ __launch_bounds__(256) void cvt_kernel(
    const float* __restrict__ x,  const float* __restrict__ wq,
    const float* __restrict__ wk, const float* __restrict__ wv,
    const float* __restrict__ wo)
{
    size_t i = (size_t)blockIdx.x * 256 + threadIdx.x;
    const float* src; __half* dst; size_t off;
    if (i < 524288)       { src = x;  dst = g_xh;  off = i; }
    else if (i < 1572864) { src = wq; dst = g_wqh; off = i - 524288; }
    else if (i < 1703936) { src = wk; dst = g_wkh; off = i - 1572864; }
    else if (i < 1835008) { src = wv; dst = g_wvh; off = i - 1703936; }
    else                  { src = wo; dst = g_woh; off = i - 1835008; }
    float4 v = ((const float4*)src)[off];
    ((uint2*)dst)[off] = make_uint2(pack_h2(v.x, v.y), pack_h2(v.z, v.w));
}

// ---------------------------------------------------------------------------
// FP16 GEMM core (R10 champion): BK=64, 512 threads / 16 warps,
// warp tile 16(M) x 64(N), 3-stage cp.async, 96KB dynamic smem.
// Smem rows: 64 halves = 128B = 8 chunks of 16B, swizzle c ^ (r&7).
// ---------------------------------------------------------------------------
#define GEMM_SMEM 98304
#define STAGE_B   16384
#define BOFF      49152

template <bool HOUT>
__device__ __forceinline__ void gemm_h_core(
    const __half* __restrict__ A, const __half* __restrict__ Bw,
    const float* __restrict__ bias, float* __restrict__ Cf, __half* __restrict__ Ch,
    int K, int ldc, int by, int colbase)
{
    extern __shared__ uint32_t Sg[];

    const int tid  = threadIdx.x;
    const int wid  = tid >> 5;
    const int lane = tid & 31;
    const int wm   = wid & 7;
    const int wn   = wid >> 3;
    const int g    = lane >> 2;
    const int t    = lane & 3;

    const __half* Ag = A + (size_t)(by * 128) * K;
    const uint32_t sb = smem_u32(Sg);

    const int r  = tid >> 2;
    const int c0 = (tid & 3) * 2;
    const int rsw = r & 7;
    const uint32_t adA0 = sb + r * 128 + ((((c0 + 0) ^ rsw)) << 4);
    const uint32_t adA1 = sb + r * 128 + ((((c0 + 1) ^ rsw)) << 4);
    const __half* arow = Ag + (size_t)r * K + c0 * 8;
    const __half* brow = Bw + (size_t)r * K + c0 * 8;

    const int lane15 = lane & 15;
    const int hiA  = lane >> 4;
    const int rowA = wm * 16 + lane15;
    const uint32_t offA = (uint32_t)rowA * 128;
    const int swA = rowA & 7;
    const int hiB = (lane >> 3) & 1;
    const int rowBb = wn * 64 + ((lane >> 4) & 1) * 8 + (lane & 7);

    float acc[8][4];
#pragma unroll
    for (int nt = 0; nt < 8; nt++)
#pragma unroll
        for (int i = 0; i < 4; i++) acc[nt][i] = 0.0f;

    const int niter = K >> 6;

#pragma unroll
    for (int s = 0; s < 2; s++) {
        const uint32_t bo = s * STAGE_B;
        CP16(adA0 + bo, arow + s * 64);
        CP16(adA1 + bo, arow + s * 64 + 8);
        CP16(adA0 + bo + BOFF, brow + s * 64);
        CP16(adA1 + bo + BOFF, brow + s * 64 + 8);
        CP_COMMIT();
    }

    for (int it = 0; it < niter; it++) {
        const int buf = it % 3;
        if (it + 1 < niter) { CP_WAIT(1); } else { CP_WAIT(0); }
        __syncthreads();

        if (it + 2 < niter) {
            const int s = it + 2;
            const uint32_t bo = (s % 3) * STAGE_B;
            CP16(adA0 + bo, arow + (size_t)s * 64);
            CP16(adA1 + bo, arow + (size_t)s * 64 + 8);
            CP16(adA0 + bo + BOFF, brow + (size_t)s * 64);
            CP16(adA1 + bo + BOFF, brow + (size_t)s * 64 + 8);
            CP_COMMIT();
        }

        const uint32_t sa  = sb + buf * STAGE_B;
        const uint32_t sbb = sa + BOFF;

#pragma unroll
        for (int ks = 0; ks < 4; ks++) {
            unsigned a[4], b[8][2];
            const int cA = 2 * ks + hiA;
            LDSM_X4(a[0], a[1], a[2], a[3], sa + offA + (((cA ^ swA)) << 4));
            const int cB = 2 * ks + hiB;
#pragma unroll
            for (int p = 0; p < 4; p++) {
                const int rowB = rowBb + p * 16;
                LDSM_X4(b[2 * p][0], b[2 * p][1], b[2 * p + 1][0], b[2 * p + 1][1],
                        sbb + (uint32_t)rowB * 128 + (((cB ^ (rowB & 7))) << 4));
            }
#pragma unroll
            for (int nt = 0; nt < 8; nt++)
                mma_f16(acc[nt], a, b[nt]);
        }
    }

    {
        const int row0 = by * 128 + wm * 16 + g;
#pragma unroll
        for (int nt = 0; nt < 8; nt++) {
            const int col = wn * 64 + nt * 8 + 2 * t;
            const float b0 = bias[col], b1 = bias[col + 1];
            if (HOUT) {
                *(unsigned*)(Ch + (size_t)row0 * ldc + colbase + col) =
                    pack_h2(acc[nt][0] + b0, acc[nt][1] + b1);
                *(unsigned*)(Ch + (size_t)(row0 + 8) * ldc + colbase + col) =
                    pack_h2(acc[nt][2] + b0, acc[nt][3] + b1);
            } else {
                float2 o0 = make_float2(acc[nt][0] + b0, acc[nt][1] + b1);
                float2 o1 = make_float2(acc[nt][2] + b0, acc[nt][3] + b1);
                *(float2*)(Cf + (size_t)row0 * ldc + colbase + col) = o0;
                *(float2*)(Cf + (size_t)(row0 + 8) * ldc + colbase + col) = o1;
            }
        }
    }
}

// Merged QKV projection -> fp16 qkv buffer
__global__ __launch_bounds__(512, 1) void gemm_qkv(
    const float* __restrict__ bq, const float* __restrict__ bk,
    const float* __restrict__ bv)
{
    const int bx = blockIdx.x;
    const __half* W; const float* bias; int wt, seg;
    if (bx < 32)      { W = g_wqh; bias = bq; wt = bx;      seg = 0; }
    else if (bx < 36) { W = g_wkh; bias = bk; wt = bx - 32; seg = K_OFF; }
    else              { W = g_wvh; bias = bv; wt = bx - 36; seg = V_OFF; }
    gemm_h_core<true>(g_xh, W + (size_t)wt * 128 * DM, bias + wt * 128,
                      nullptr, g_qkvh, DM, QKV_N, blockIdx.y, seg + wt * 128);
}

// Output projection (f32 out)
__global__ __launch_bounds__(512, 1) void gemm_out(
    const float* __restrict__ bias, float* __restrict__ C)
{
    gemm_h_core<false>(g_attnh, g_woh + (size_t)blockIdx.x * 128 * (NH * HD),
                       bias + blockIdx.x * 128, C, nullptr,
                       NH * HD, DM, blockIdx.y, blockIdx.x * 128);
}

// ---------------------------------------------------------------------------
// Fully-fp16 flash attention, Q staged in smem (frees 32 regs -> 2 CTAs/SM).
// CTA = (32 queries, kv-head, batch), 256 threads, warp = head.
// Smem: KV 16KB (double-buffered K+V) + Q 32KB = 48KB.
// Q rows: 512 halves = 1024B = 64 chunks of 16B, swizzle c ^ (q&7).
// ---------------------------------------------------------------------------
__global__ __launch_bounds__(256, 2) void attn_h_kernel(
    const __half* __restrict__ qkv, const float* __restrict__ sinks,
    __half* __restrict__ out)
{
    __shared__ uint32_t KV[4096];     // 16KB: K 2x4KB @0, V 2x4KB @8192B... (word idx)
    __shared__ uint32_t QS[8192];     // 32KB: 32 q-rows x 1024B

    const int q0  = blockIdx.x * 32;
    const int hk  = blockIdx.y;
    const int b   = blockIdx.z;
    const int tid = threadIdx.x;
    const int wid = tid >> 5;
    const int lane = tid & 31;
    const int g = lane >> 2;
    const int t = lane & 3;

    const int kbase = (q0 >= 128) ? (q0 - 128) : 0;
    const int nch = (q0 + 32 - kbase) >> 5;
    const uint32_t kvb = smem_u32(KV);
    const uint32_t qsb = smem_u32(QS);

    // --- stage Q into smem via cp.async (coalesced) ---
    {
        const int qr = tid >> 3;                 // 0..31
        const int qc = tid & 7;                  // chunk group
        const __half* qsrc = qkv + ((size_t)(b * SEQ + q0 + qr)) * QKV_N + hk * 512;
        const uint32_t qdst = qsb + (uint32_t)qr * 1024;
        const int qsw = qr & 7;
#pragma unroll
        for (int j = 0; j < 8; j++) {
            const int c = qc + j * 8;
            CP16(qdst + (((c ^ qsw)) << 4), qsrc + c * 8);
        }
    }

    const float sink = sinks[hk * GQA + wid];
    float m[2][2], l[2][2];
#pragma unroll
    for (int mt = 0; mt < 2; mt++) { m[mt][0] = sink; m[mt][1] = sink; l[mt][0] = 0.f; l[mt][1] = 0.f; }

    float o[2][8][4];
#pragma unroll
    for (int mt = 0; mt < 2; mt++)
#pragma unroll
        for (int nt = 0; nt < 8; nt++)
#pragma unroll
            for (int i = 0; i < 4; i++) o[mt][nt][i] = 0.0f;

    const int lr = tid >> 3;
    const int lc = tid & 7;
    const uint32_t koff = (uint32_t)lr * 128 + (((lc ^ (lr & 7))) << 4);
    const __half* kg = qkv + K_OFF + hk * 64 + lc * 8;
    const __half* vg = qkv + V_OFF + hk * 64 + lc * 8;

    // prologue: Q (above) + chunk 0 K/V in one group
    {
        size_t rbase = ((size_t)(b * SEQ + kbase + lr)) * QKV_N;
        CP16(kvb + koff, kg + rbase);
        CP16(kvb + 8192 + koff, vg + rbase);
        CP_COMMIT();
    }

    // Q ldmatrix geometry: warp head = wid, A-frag rows = mt*16 + lane15
    const int lane15 = lane & 15;
    const int hiA = lane >> 4;

    for (int ch = 0; ch < nch; ch++) {
        const int kb = kbase + ch * KC;
        const uint32_t kbuf = kvb + (ch & 1) * 4096;
        const uint32_t vbuf = kbuf + 8192;

        CP_WAIT(0);
        __syncthreads();

        if (ch + 1 < nch) {
            size_t rbase = ((size_t)(b * SEQ + kb + KC + lr)) * QKV_N;
            uint32_t nb = kvb + ((ch + 1) & 1) * 4096;
            CP16(nb + koff, kg + rbase);
            CP16(nb + 8192 + koff, vg + rbase);
            CP_COMMIT();
        }

        float sc[2][4][4];
#pragma unroll
        for (int mt = 0; mt < 2; mt++)
#pragma unroll
            for (int nt = 0; nt < 4; nt++)
#pragma unroll
                for (int i = 0; i < 4; i++) sc[mt][nt][i] = 0.0f;

#pragma unroll
        for (int ks = 0; ks < 4; ks++) {
            // K fragments from smem
            unsigned bf[4][2];
            const int cB = 2 * ks + ((lane >> 3) & 1);
#pragma unroll
            for (int p = 0; p < 2; p++) {
                const int rowB = ((lane >> 4) & 1) * 8 + (lane & 7) + p * 16;
                LDSM_X4(bf[2 * p][0], bf[2 * p][1], bf[2 * p + 1][0], bf[2 * p + 1][1],
                        kbuf + (uint32_t)rowB * 128 + (((cB ^ (rowB & 7))) << 4));
            }
            // Q fragments from smem (per-chunk reload; frees persistent regs)
            const int cQ = wid * 8 + 2 * ks + hiA;
#pragma unroll
            for (int mt = 0; mt < 2; mt++) {
                unsigned a[4];
                const int rowQ = mt * 16 + lane15;
                LDSM_X4(a[0], a[1], a[2], a[3],
                        qsb + (uint32_t)rowQ * 1024 + (((cQ ^ (rowQ & 7))) << 4));
#pragma unroll
                for (int nt = 0; nt < 4; nt++)
                    mma_f16(sc[mt][nt], a, bf[nt]);
            }
        }

#pragma unroll
        for (int mt = 0; mt < 2; mt++) {
            const int qr0 = q0 + mt * 16 + g;
            const int qr1 = qr0 + 8;
            float mx0 = -1e30f, mx1 = -1e30f;
#pragma unroll
            for (int nt = 0; nt < 4; nt++) {
                const int k0c = kb + nt * 8 + 2 * t;
                const int k1c = k0c + 1;
                float s0 = sc[mt][nt][0] * 0.125f;
                float s1 = sc[mt][nt][1] * 0.125f;
                float s2 = sc[mt][nt][2] * 0.125f;
                float s3 = sc[mt][nt][3] * 0.125f;
                s0 = (k0c <= qr0 && qr0 - k0c < WIN) ? s0 : -1e30f;
                s1 = (k1c <= qr0 && qr0 - k1c < WIN) ? s1 : -1e30f;
                s2 = (k0c <= qr1 && qr1 - k0c < WIN) ? s2 : -1e30f;
                s3 = (k1c <= qr1 && qr1 - k1c < WIN) ? s3 : -1e30f;
                sc[mt][nt][0] = s0; sc[mt][nt][1] = s1;
                sc[mt][nt][2] = s2; sc[mt][nt][3] = s3;
                mx0 = fmaxf(mx0, fmaxf(s0, s1));
                mx1 = fmaxf(mx1, fmaxf(s2, s3));
            }
            mx0 = fmaxf(mx0, __shfl_xor_sync(0xFFFFFFFFu, mx0, 1));
            mx0 = fmaxf(mx0, __shfl_xor_sync(0xFFFFFFFFu, mx0, 2));
            mx1 = fmaxf(mx1, __shfl_xor_sync(0xFFFFFFFFu, mx1, 1));
            mx1 = fmaxf(mx1, __shfl_xor_sync(0xFFFFFFFFu, mx1, 2));

            const float mn0 = fmaxf(m[mt][0], mx0);
            const float mn1 = fmaxf(m[mt][1], mx1);
            const float r0 = __expf(m[mt][0] - mn0);
            const float r1 = __expf(m[mt][1] - mn1);
            m[mt][0] = mn0; m[mt][1] = mn1;
            l[mt][0] *= r0; l[mt][1] *= r1;
#pragma unroll
            for (int nt = 0; nt < 8; nt++) {
                o[mt][nt][0] *= r0; o[mt][nt][1] *= r0;
                o[mt][nt][2] *= r1; o[mt][nt][3] *= r1;
            }
#pragma unroll
            for (int nt = 0; nt < 4; nt++) {
                float p0 = __expf(sc[mt][nt][0] - mn0);
                float p1 = __expf(sc[mt][nt][1] - mn0);
                float p2 = __expf(sc[mt][nt][2] - mn1);
                float p3 = __expf(sc[mt][nt][3] - mn1);
                l[mt][0] += p0 + p1;
                l[mt][1] += p2 + p3;
                sc[mt][nt][0] = p0; sc[mt][nt][1] = p1;
                sc[mt][nt][2] = p2; sc[mt][nt][3] = p3;
            }
        }

#pragma unroll
        for (int pk = 0; pk < 2; pk++) {
            unsigned pa[2][4];
#pragma unroll
            for (int mt = 0; mt < 2; mt++) {
                pa[mt][0] = pack_h2(sc[mt][2 * pk][0],     sc[mt][2 * pk][1]);
                pa[mt][1] = pack_h2(sc[mt][2 * pk][2],     sc[mt][2 * pk][3]);
                pa[mt][2] = pack_h2(sc[mt][2 * pk + 1][0], sc[mt][2 * pk + 1][1]);
                pa[mt][3] = pack_h2(sc[mt][2 * pk + 1][2], sc[mt][2 * pk + 1][3]);
            }
            const int rowV = pk * 16 + (lane & 15);
            const uint32_t vrow = vbuf + (uint32_t)rowV * 128;
            const int swV = rowV & 7;
#pragma unroll
            for (int nt = 0; nt < 8; nt++) {
                unsigned bv[2];
                LDSM_X2T(bv[0], bv[1], vrow + (((nt ^ swV)) << 4));
#pragma unroll
                for (int mt = 0; mt < 2; mt++)
                    mma_f16(o[mt][nt], pa[mt], bv);
            }
        }
    }

#pragma unroll
    for (int mt = 0; mt < 2; mt++) {
        float l0 = l[mt][0], l1 = l[mt][1];
        l0 += __shfl_xor_sync(0xFFFFFFFFu, l0, 1);
        l0 += __shfl_xor_sync(0xFFFFFFFFu, l0, 2);
        l1 += __shfl_xor_sync(0xFFFFFFFFu, l1, 1);
        l1 += __shfl_xor_sync(0xFFFFFFFFu, l1, 2);
        const float inv0 = 1.0f / (l0 + __expf(sink - m[mt][0]));
        const float inv1 = 1.0f / (l1 + __expf(sink - m[mt][1]));

        const int qr0 = q0 + mt * 16 + g;
        __half* orow0 = out + ((size_t)(b * SEQ + qr0)) * (NH * HD) + (hk * GQA + wid) * HD;
        __half* orow1 = orow0 + (size_t)8 * (NH * HD);
#pragma unroll
        for (int nt = 0; nt < 8; nt++) {
            *(unsigned*)(orow0 + nt * 8 + 2 * t) = pack_h2(o[mt][nt][0] * inv0, o[mt][nt][1] * inv0);
            *(unsigned*)(orow1 + nt * 8 + 2 * t) = pack_h2(o[mt][nt][2] * inv1, o[mt][nt][3] * inv1);
        }
    }
}

// ---------------------------------------------------------------------------
// kernel_launch
// ---------------------------------------------------------------------------
extern "C" void kernel_launch(void* const* d_in, const int* in_sizes, int n_in,
                              void* d_out, int out_size)
{
    const float* x    = (const float*)d_in[0];
    const float* Wq   = (const float*)d_in[1];
    const float* bq   = (const float*)d_in[2];
    const float* Wk   = (const float*)d_in[3];
    const float* bk   = (const float*)d_in[4];
    const float* Wv   = (const float*)d_in[5];
    const float* bv   = (const float*)d_in[6];
    const float* Wo   = (const float*)d_in[7];
    const float* bo   = (const float*)d_in[8];
    const float* sinks = (const float*)d_in[9];
    float* out = (float*)d_out;

    __half* qkvh = nullptr;
    __half* attnh = nullptr;
    cudaGetSymbolAddress((void**)&qkvh, g_qkvh);
    cudaGetSymbolAddress((void**)&attnh, g_attnh);

    static bool attr_set = false;
    if (!attr_set) {
        cudaFuncSetAttribute(gemm_qkv, cudaFuncAttributeMaxDynamicSharedMemorySize, GEMM_SMEM);
        cudaFuncSetAttribute(gemm_out, cudaFuncAttributeMaxDynamicSharedMemorySize, GEMM_SMEM);
        attr_set = true;
    }

    const int M = BATCH * SEQ;   // 2048

    cvt_kernel<<<CVT_TOTAL4 / 256, 256>>>(x, Wq, Wk, Wv, Wo);

    {
        dim3 grid(40, M / 128);
        gemm_qkv<<<grid, 512, GEMM_SMEM>>>(bq, bk, bv);
    }
    {
        dim3 grid(SEQ / 32, NHK, BATCH);
        attn_h_kernel<<<grid, 256>>>(qkvh, sinks, attnh);
    }
    {
        dim3 grid(DM / 128, M / 128);
        gemm_out<<<grid, 512, GEMM_SMEM>>>(bo, out);
    }
}